// round 9
// baseline (speedup 1.0000x reference)
#include <cuda_runtime.h>
#include <cuda_bf16.h>
#include <cstdint>

#define D        256
#define KCODES   8192
#define BM       256                 // rows per CTA (8 warps x 2 m16 tiles)
#define BN       128                 // codes per chunk
#define NCHUNK   (KCODES / BN)
#define THREADS  256
#define NROWS    32768
#define NCAND    16                  // candidates per row (4 lanes x depth 4)

// ---- smem: double-buffered int8 B chunk + c2 ----
#define BROWB     272                              // bytes per B row (256 data + 16 pad)
#define BUF_BYTES (BN * BROWB)                     // 34816
#define C2_OFF    (2 * BUF_BYTES)                  // [2][128] f32
#define SMEM_TOTAL (C2_OFF + 2 * BN * 4 + 256)

__device__ __align__(16) float g_c2[KCODES];
__device__ __align__(16) int8_t g_cbi[KCODES * D];   // int8 codebook (2MB)
__device__ int g_cand[NROWS * NCAND];

// ======================= helpers =======================
__device__ __forceinline__ uint32_t smem_u32(const void* p) {
    uint32_t a;
    asm("{ .reg .u64 t; cvta.to.shared.u64 t, %1; cvt.u32.u64 %0, t; }" : "=r"(a) : "l"(p));
    return a;
}
__device__ __forceinline__ uint32_t q4(float4 v, float s) {
    int x = __float2int_rn(v.x * s), y = __float2int_rn(v.y * s);
    int z = __float2int_rn(v.z * s), w = __float2int_rn(v.w * s);
    return (uint32_t)(x & 0xFF) | ((uint32_t)(y & 0xFF) << 8)
         | ((uint32_t)(z & 0xFF) << 16) | ((uint32_t)w << 24);
}
__device__ __forceinline__ float max4(float4 v) {
    return fmaxf(fmaxf(fabsf(v.x), fabsf(v.y)), fmaxf(fabsf(v.z), fabsf(v.w)));
}
// monotonic sortable key: top 19 bits of order-preserved float, low 13 bits = idx
__device__ __forceinline__ uint32_t mkey(float s, int gi) {
    uint32_t u = __float_as_uint(s);
    uint32_t m = u ^ (uint32_t)(((int)u >> 31) | 0x80000000);
    return (m & 0xFFFFE000u) | (uint32_t)gi;
}
// sorted depth-4 insert (t[0] best)
__device__ __forceinline__ void ins4(uint32_t* t, uint32_t k) {
    bool b1 = k < t[0], b2 = k < t[1], b3 = k < t[2], b4 = k < t[3];
    t[3] = b3 ? t[2] : (b4 ? k : t[3]);
    t[2] = b2 ? t[1] : (b3 ? k : t[2]);
    t[1] = b1 ? t[0] : (b2 ? k : t[1]);
    t[0] = b1 ? k : t[0];
}

#define CP_ASYNC16(dst, src) \
    asm volatile("cp.async.ca.shared.global [%0], [%1], 16;" :: "r"(dst), "l"(src))
#define CP_COMMIT() asm volatile("cp.async.commit_group;" ::: "memory")
#define CP_WAIT1()  asm volatile("cp.async.wait_group 1;" ::: "memory")

#define MMA_S8(Cr, Ar, B0, B1) \
    asm volatile("mma.sync.aligned.m16n8k32.row.col.s32.s8.s8.s32 " \
        "{%0,%1,%2,%3}, {%4,%5,%6,%7}, {%8,%9}, {%0,%1,%2,%3};" \
        : "+r"((Cr)[0]), "+r"((Cr)[1]), "+r"((Cr)[2]), "+r"((Cr)[3]) \
        : "r"((Ar)[0]), "r"((Ar)[1]), "r"((Ar)[2]), "r"((Ar)[3]), \
          "r"(B0), "r"(B1))

#define LDSM_X4(r0, r1, r2, r3, addr) \
    asm volatile("ldmatrix.sync.aligned.m8n8.x4.shared.b16 {%0,%1,%2,%3}, [%4];" \
        : "=r"(r0), "=r"(r1), "=r"(r2), "=r"(r3) : "r"(addr))

// ---------------- kernel 0: codebook f32 -> int8 ----------------
__global__ void prep_kernel(const float* __restrict__ cb) {
    int t = blockIdx.x * blockDim.x + threadIdx.x;     // 0..262143
    const float4* s4 = (const float4*)cb;
    float4 v0 = s4[t * 2];
    float4 v1 = s4[t * 2 + 1];
    ((uint2*)g_cbi)[t] = make_uint2(q4(v0, 127.0f), q4(v1, 127.0f));
}

// ---------------- kernel 1: codebook squared norms (exact f32) ----------------
__global__ void c2_kernel(const float* __restrict__ cb) {
    int warp = (blockIdx.x * blockDim.x + threadIdx.x) >> 5;
    int lane = threadIdx.x & 31;
    if (warp >= KCODES) return;
    const float4* row = (const float4*)(cb + (size_t)warp * D);
    float4 a = row[lane];
    float4 b = row[lane + 32];
    float s = a.x*a.x + a.y*a.y + a.z*a.z + a.w*a.w
            + b.x*b.x + b.y*b.y + b.z*b.z + b.w*b.w;
    #pragma unroll
    for (int off = 16; off; off >>= 1) s += __shfl_down_sync(0xffffffffu, s, off);
    if (lane == 0) g_c2[warp] = s;
}

// ---------------- kernel 2: int8 IMMA candidate search ----------------
extern __shared__ char smem_raw[];

__device__ __forceinline__ void load_chunk_async(uint32_t sbase, int buf,
                                                 int n0, int tid) {
    uint32_t dstb = sbase + buf * BUF_BYTES;
    const int8_t* cbi = g_cbi;
    #pragma unroll
    for (int i = 0; i < 8; i++) {
        int e = i * THREADS + tid;            // 0..2047 16B-units (128 rows x 16 units)
        int n = e >> 4, u = e & 15;
        uint32_t dst = dstb + n * BROWB + u * 16;
        const int8_t* src = cbi + (size_t)(n0 + n) * D + u * 16;
        CP_ASYNC16(dst, src);
    }
    if (tid < 32) {
        uint32_t dst = sbase + C2_OFF + buf * 512 + tid * 16;
        CP_ASYNC16(dst, (const float*)g_c2 + n0 + tid * 4);
    }
}

__global__ __launch_bounds__(THREADS, 1)
void vq_main(const float* __restrict__ h)
{
    const uint32_t sbase = smem_u32(smem_raw);
    const float* c2s = (const float*)(smem_raw + C2_OFF);
    const int tid  = threadIdx.x;
    const int lane = tid & 31;
    const int rowbase = blockIdx.x * BM + (tid >> 5) * 32;

    // ---- prefetch chunk 0 ----
    load_chunk_async(sbase, 0, 0, tid);
    CP_COMMIT();

    // ---- pass 1: per-row abs-max over this lane's slice ----
    float rmax[4] = {0.f, 0.f, 0.f, 0.f};
    #pragma unroll
    for (int mt = 0; mt < 2; mt++) {
        #pragma unroll
        for (int k = 0; k < 8; k++) {
            int r = rowbase + mt * 16 + (lane >> 2);
            int c = k * 32 + (lane & 3) * 4;
            const float* p0 = h + (size_t)r * D + c;
            const float* p1 = h + (size_t)(r + 8) * D + c;
            rmax[mt*2]   = fmaxf(rmax[mt*2],   fmaxf(max4(*(const float4*)p0),
                                                     max4(*(const float4*)(p0 + 16))));
            rmax[mt*2+1] = fmaxf(rmax[mt*2+1], fmaxf(max4(*(const float4*)p1),
                                                     max4(*(const float4*)(p1 + 16))));
        }
    }
    float sxq[4], fsc[4];
    #pragma unroll
    for (int s = 0; s < 4; s++) {
        rmax[s] = fmaxf(rmax[s], __shfl_xor_sync(0xffffffffu, rmax[s], 1));
        rmax[s] = fmaxf(rmax[s], __shfl_xor_sync(0xffffffffu, rmax[s], 2));
        rmax[s] = fmaxf(rmax[s], 1e-20f);
        sxq[s] = 127.0f / rmax[s];
        fsc[s] = 2.0f * rmax[s] / 16129.0f;   // 2 * (rmax/127) * (1/127)
    }

    // ---- pass 2: quantize A fragments (2 mt x 8 k32 x 4 regs) ----
    uint32_t a[2][8][4];
    #pragma unroll
    for (int mt = 0; mt < 2; mt++) {
        #pragma unroll
        for (int k = 0; k < 8; k++) {
            int r = rowbase + mt * 16 + (lane >> 2);
            int c = k * 32 + (lane & 3) * 4;
            const float* p0 = h + (size_t)r * D + c;
            const float* p1 = h + (size_t)(r + 8) * D + c;
            a[mt][k][0] = q4(*(const float4*)p0,        sxq[mt*2]);
            a[mt][k][1] = q4(*(const float4*)p1,        sxq[mt*2+1]);
            a[mt][k][2] = q4(*(const float4*)(p0 + 16), sxq[mt*2]);
            a[mt][k][3] = q4(*(const float4*)(p1 + 16), sxq[mt*2+1]);
        }
    }

    const uint32_t laneoff = (uint32_t)((((lane >> 4) & 1) * 8 + (lane & 7)) * BROWB
                                        + ((lane >> 3) & 1) * 16);

    // ---- per-lane top-4 keys for 4 row-slots ----
    uint32_t tk[4][4];
    #pragma unroll
    for (int s = 0; s < 4; s++)
        #pragma unroll
        for (int d = 0; d < 4; d++) tk[s][d] = 0xFFFFFFFFu;

    for (int ch = 0; ch < NCHUNK; ch++) {
        const int buf = ch & 1;
        const int n0  = ch * BN;

        __syncthreads();
        if (ch + 1 < NCHUNK) load_chunk_async(sbase, buf ^ 1, n0 + BN, tid);
        CP_COMMIT();
        CP_WAIT1();
        __syncthreads();

        const uint32_t bsm = sbase + buf * BUF_BYTES + laneoff;
        const float* c2p = c2s + buf * BN;

        #pragma unroll
        for (int pr = 0; pr < 8; pr++) {            // 16 cols per pr
            int C[4][4];
            #pragma unroll
            for (int q = 0; q < 4; q++)
                #pragma unroll
                for (int e = 0; e < 4; e++) C[q][e] = 0;

            const uint32_t bpr = bsm + (uint32_t)(pr * 16) * BROWB;
            #pragma unroll
            for (int k = 0; k < 8; k++) {
                uint32_t b0, b1, b2, b3;
                LDSM_X4(b0, b1, b2, b3, bpr + k * 32);
                MMA_S8(C[0], a[0][k], b0, b1);
                MMA_S8(C[1], a[0][k], b2, b3);
                MMA_S8(C[2], a[1][k], b0, b1);
                MMA_S8(C[3], a[1][k], b2, b3);
            }

            // epilogue: score = c2 - fsc*dot_int, depth-4 key insert
            #pragma unroll
            for (int mt = 0; mt < 2; mt++) {
                #pragma unroll
                for (int nh = 0; nh < 2; nh++) {
                    const int* f = C[mt * 2 + nh];
                    int lc = pr * 16 + nh * 8 + (lane & 3) * 2;
                    int gi = n0 + lc;
                    float ca = c2p[lc], cb2 = c2p[lc + 1];
                    int sl0 = mt * 2, sl1 = mt * 2 + 1;
                    ins4(tk[sl0], mkey(fmaf(-fsc[sl0], (float)f[0], ca),  gi));
                    ins4(tk[sl0], mkey(fmaf(-fsc[sl0], (float)f[1], cb2), gi + 1));
                    ins4(tk[sl1], mkey(fmaf(-fsc[sl1], (float)f[2], ca),  gi));
                    ins4(tk[sl1], mkey(fmaf(-fsc[sl1], (float)f[3], cb2), gi + 1));
                }
            }
        }
    }

    // ---- publish 16 candidates per row (4 lanes x depth 4) ----
    #pragma unroll
    for (int s = 0; s < 4; s++) {
        int row  = rowbase + (s >> 1) * 16 + (lane >> 2) + (s & 1) * 8;
        int base = row * NCAND + (lane & 3) * 4;
        #pragma unroll
        for (int d = 0; d < 4; d++)
            g_cand[base + d] = (int)(tk[s][d] & 0x1FFFu);
    }
}

// ---------------- kernel 3: exact fp32 rescore + gather ----------------
__global__ __launch_bounds__(256)
void rescore_kernel(const float* __restrict__ h, const float* __restrict__ cb,
                    float* __restrict__ outQ, float* __restrict__ outIdxF,
                    int* __restrict__ outIdxI)
{
    const int row  = blockIdx.x * 8 + (threadIdx.x >> 5);
    const int lane = threadIdx.x & 31;

    const float4* hr = (const float4*)(h + (size_t)row * D);
    float4 h0 = hr[lane], h1 = hr[lane + 32];

    float bd = 3.4e38f;
    int   bi = KCODES;
    #pragma unroll
    for (int j = 0; j < NCAND; j++) {
        int ci = g_cand[row * NCAND + j];
        const float4* cr = (const float4*)(cb + (size_t)ci * D);
        float4 c0 = cr[lane], c1 = cr[lane + 32];
        float dot = h0.x*c0.x + h0.y*c0.y + h0.z*c0.z + h0.w*c0.w
                  + h1.x*c1.x + h1.y*c1.y + h1.z*c1.z + h1.w*c1.w;
        #pragma unroll
        for (int o = 16; o; o >>= 1) dot += __shfl_xor_sync(0xffffffffu, dot, o);
        float dist = fmaf(-2.0f, dot, g_c2[ci]);
        if (dist < bd || (dist == bd && ci < bi)) { bd = dist; bi = ci; }
    }

    const float4* wr = (const float4*)(cb + (size_t)bi * D);
    if (outQ) {
        float4* o4 = (float4*)(outQ + (size_t)row * D);
        o4[lane]      = wr[lane];
        o4[lane + 32] = wr[lane + 32];
    }
    if (lane == 0) {
        if (outIdxF) outIdxF[row] = (float)bi;
        if (outIdxI) outIdxI[row] = bi;
    }
}

// ---------------- launch ----------------
extern "C" void kernel_launch(void* const* d_in, const int* in_sizes, int n_in,
                              void* d_out, int out_size)
{
    const float* h  = (const float*)d_in[0];
    const float* cb = (const float*)d_in[1];
    const int N = in_sizes[0] / D;   // 32768 rows

    prep_kernel<<<KCODES * D / 8 / 256, 256>>>(cb);
    c2_kernel<<<KCODES / 8, 256>>>(cb);

    cudaFuncSetAttribute(vq_main, cudaFuncAttributeMaxDynamicSharedMemorySize,
                         SMEM_TOTAL);
    vq_main<<<N / BM, THREADS, SMEM_TOTAL>>>(h);

    float* outQ    = nullptr;
    float* outIdxF = nullptr;
    int*   outIdxI = nullptr;
    long long nd = (long long)N * D;
    if (out_size >= nd) {
        outQ = (float*)d_out;
        if (out_size >= nd + N) outIdxF = (float*)d_out + nd;
    } else {
        outIdxI = (int*)d_out;
    }

    rescore_kernel<<<N / 8, 256>>>(h, cb, outQ, outIdxF, outIdxI);
}